// round 2
// baseline (speedup 1.0000x reference)
#include <cuda_runtime.h>

#define N_NODES 100000
#define N_EDGES 1600000
#define HID 64
#define NGRAPH 128
#define DENSE 128

// Scratch (static __device__ allocations are allowed)
__device__ float g_buf0[N_NODES * HID];   // h (post-relu conv output / gemm input)
__device__ float g_buf1[N_NODES * HID];   // g = (h@W)*dinv[row] (gather buffer)
__device__ int   g_cnt[N_NODES];
__device__ int   g_rowptr[N_NODES + 1];
__device__ int   g_cursor[N_NODES];
__device__ int   g_col[N_EDGES];
__device__ float g_dinv[N_NODES];
__device__ float g_pooled[NGRAPH * HID];

// ---------------------------------------------------------------- CSR build
__global__ void zero_cnt_k() {
    int i = blockIdx.x * blockDim.x + threadIdx.x;
    if (i < N_NODES) g_cnt[i] = 0;
}

__global__ void hist_k(const int* __restrict__ ei) {
    int e = blockIdx.x * blockDim.x + threadIdx.x;
    if (e < N_EDGES) {
        int d = ei[N_EDGES + e];   // edge_index[1][e]
        atomicAdd(&g_cnt[d], 1);
    }
}

// Single-block exclusive scan over g_cnt -> g_rowptr / g_cursor. 4 items/thread.
__global__ void scan_k() {
    __shared__ int sh[1024];
    __shared__ int carry_s;
    int tid = threadIdx.x;
    if (tid == 0) carry_s = 0;
    __syncthreads();
    for (int base = 0; base < N_NODES; base += 4096) {
        int v[4];
        int local = 0;
#pragma unroll
        for (int q = 0; q < 4; q++) {
            int i = base + tid * 4 + q;
            v[q] = (i < N_NODES) ? g_cnt[i] : 0;
            local += v[q];
        }
        sh[tid] = local;
        // Hillis-Steele inclusive scan of per-thread sums
        for (int off = 1; off < 1024; off <<= 1) {
            __syncthreads();
            int t = (tid >= off) ? sh[tid - off] : 0;
            __syncthreads();
            sh[tid] += t;
        }
        __syncthreads();
        int incl = sh[tid];
        int total = sh[1023];
        int carry = carry_s;
        int run = carry + incl - local;   // exclusive for this thread's first item
#pragma unroll
        for (int q = 0; q < 4; q++) {
            int i = base + tid * 4 + q;
            if (i < N_NODES) {
                g_rowptr[i] = run;
                g_cursor[i] = run;
                run += v[q];
            }
        }
        __syncthreads();
        if (tid == 0) carry_s = carry + total;
        __syncthreads();
    }
    if (threadIdx.x == 0) g_rowptr[N_NODES] = carry_s;
}

__global__ void fill_k(const int* __restrict__ ei) {
    int e = blockIdx.x * blockDim.x + threadIdx.x;
    if (e < N_EDGES) {
        int s = ei[e];
        int d = ei[N_EDGES + e];
        int pos = atomicAdd(&g_cursor[d], 1);
        g_col[pos] = s;
    }
}

__global__ void dinv_k() {
    int i = blockIdx.x * blockDim.x + threadIdx.x;
    if (i < N_NODES) g_dinv[i] = rsqrtf((float)(g_cnt[i] + 1));  // +1 self loop
}

// ---------------------------------------------------------------- GEMMs
// Layer 0: x[N,3] @ W0[3,64], scaled by dinv[row] -> g_buf1
__global__ void gemm0_k(const float* __restrict__ x, const float* __restrict__ W0) {
    __shared__ float Ws[3 * HID];
    int t = threadIdx.x;
    if (t < 3 * HID) Ws[t] = W0[t];
    __syncthreads();
    int idx = blockIdx.x * blockDim.x + t;   // thread per (row, channel-pair)
    int row = idx >> 5;
    int cp  = (idx & 31) * 2;
    if (row < N_NODES) {
        float x0 = x[row * 3 + 0], x1 = x[row * 3 + 1], x2 = x[row * 3 + 2];
        float di = g_dinv[row];
        float a = (x0 * Ws[cp]     + x1 * Ws[HID + cp]     + x2 * Ws[2 * HID + cp])     * di;
        float b = (x0 * Ws[cp + 1] + x1 * Ws[HID + cp + 1] + x2 * Ws[2 * HID + cp + 1]) * di;
        *(float2*)&g_buf1[row * HID + cp] = make_float2(a, b);
    }
}

// Layers 1/2: g_buf0[N,64] @ W[64,64], scaled by dinv[row] -> g_buf1
// 64x64 tile per block (256 thr), 4x4 register tile per thread.
__global__ void gemm64_k(const float* __restrict__ W) {
    __shared__ float hs[64 * 65];
    __shared__ float ws[64 * 64];
    int t  = threadIdx.x;
    int rb = blockIdx.x * 64;
    // load W (4096 f32 = 1024 float4)
    {
        const float4* Wv = (const float4*)W;
        float4* wv = (float4*)ws;
#pragma unroll
        for (int q = 0; q < 4; q++) { int i = t + q * 256; wv[i] = Wv[i]; }
    }
    // load H rows with padding-65 for conflict-free column reads
#pragma unroll
    for (int q = 0; q < 4; q++) {
        int i = t + q * 256;              // float4 index 0..1023
        int r = i >> 4, kq = (i & 15) << 2;
        float4 v = make_float4(0.f, 0.f, 0.f, 0.f);
        if (rb + r < N_NODES) v = *(const float4*)&g_buf0[(rb + r) * HID + kq];
        hs[r * 65 + kq]     = v.x;
        hs[r * 65 + kq + 1] = v.y;
        hs[r * 65 + kq + 2] = v.z;
        hs[r * 65 + kq + 3] = v.w;
    }
    __syncthreads();
    int tx = t & 15, ty = t >> 4;
    int c0 = tx * 4, r0 = ty * 4;
    float acc[4][4] = {};
#pragma unroll
    for (int k = 0; k < 64; k++) {
        float4 b = *(const float4*)&ws[k * 64 + c0];
        float a0 = hs[(r0 + 0) * 65 + k];
        float a1 = hs[(r0 + 1) * 65 + k];
        float a2 = hs[(r0 + 2) * 65 + k];
        float a3 = hs[(r0 + 3) * 65 + k];
        acc[0][0] += a0 * b.x; acc[0][1] += a0 * b.y; acc[0][2] += a0 * b.z; acc[0][3] += a0 * b.w;
        acc[1][0] += a1 * b.x; acc[1][1] += a1 * b.y; acc[1][2] += a1 * b.z; acc[1][3] += a1 * b.w;
        acc[2][0] += a2 * b.x; acc[2][1] += a2 * b.y; acc[2][2] += a2 * b.z; acc[2][3] += a2 * b.w;
        acc[3][0] += a3 * b.x; acc[3][1] += a3 * b.y; acc[3][2] += a3 * b.z; acc[3][3] += a3 * b.w;
    }
#pragma unroll
    for (int i = 0; i < 4; i++) {
        int r = rb + r0 + i;
        if (r < N_NODES) {
            float di = g_dinv[r];
            float4 v = make_float4(acc[i][0] * di, acc[i][1] * di, acc[i][2] * di, acc[i][3] * di);
            *(float4*)&g_buf1[r * HID + c0] = v;
        }
    }
}

// ---------------------------------------------------------------- Aggregation
// One warp per dst node, 2 channels per lane. Atomic-free CSR gather.
// out[i] = relu(dinv[i] * (g[i] + sum_{src in N(i)} g[src]) + bias)
__global__ void agg_k(const float* __restrict__ bias) {
    int w    = (blockIdx.x * blockDim.x + threadIdx.x) >> 5;
    int lane = threadIdx.x & 31;
    if (w >= N_NODES) return;
    int s = g_rowptr[w];
    int e = g_rowptr[w + 1];
    float2 acc = *(const float2*)&g_buf1[w * HID + lane * 2];  // self loop (pre-scaled)
    for (int base = s; base < e; base += 32) {
        int idx = base + lane;
        int cv = (idx < e) ? g_col[idx] : 0;
        int m = e - base;
        if (m > 32) m = 32;
        for (int j = 0; j < m; j++) {
            int src = __shfl_sync(0xffffffffu, cv, j);
            float2 v = *(const float2*)&g_buf1[src * HID + lane * 2];
            acc.x += v.x;
            acc.y += v.y;
        }
    }
    float di = g_dinv[w];
    float2 bb = *(const float2*)&bias[lane * 2];
    float2 r;
    r.x = fmaxf(fmaf(acc.x, di, bb.x), 0.f);
    r.y = fmaxf(fmaf(acc.y, di, bb.y), 0.f);
    *(float2*)&g_buf0[w * HID + lane * 2] = r;
}

// ---------------------------------------------------------------- Pool + head
__global__ void pool_k(const int* __restrict__ batch) {
    int g = blockIdx.x, t = threadIdx.x;   // 128 blocks x 256 thr
    __shared__ int lo_s, hi_s;
    if (t == 0) {
        int v = g;
        int lo = 0, hi = N_NODES;
        while (lo < hi) { int m = (lo + hi) >> 1; if (batch[m] < v) lo = m + 1; else hi = m; }
        lo_s = lo;
        int v2 = g + 1;
        int lo2 = lo, hi2 = N_NODES;
        while (lo2 < hi2) { int m = (lo2 + hi2) >> 1; if (batch[m] < v2) lo2 = m + 1; else hi2 = m; }
        hi_s = lo2;
    }
    __syncthreads();
    int lo = lo_s, hi = hi_s;
    int c = t & 63, rg = t >> 6;
    float acc = 0.f;
    for (int r = lo + rg; r < hi; r += 4) acc += g_buf0[r * HID + c];
    __shared__ float sh[256];
    sh[t] = acc;
    __syncthreads();
    if (t < 64) {
        float s = sh[t] + sh[t + 64] + sh[t + 128] + sh[t + 192];
        float cntf = (float)(hi - lo);
        if (cntf < 1.f) cntf = 1.f;
        g_pooled[g * HID + t] = s / cntf;
    }
}

__global__ void fc_k(const float* __restrict__ fc1w, const float* __restrict__ fc1b,
                     const float* __restrict__ fc2w, const float* __restrict__ fc2b,
                     float* __restrict__ out) {
    int g = blockIdx.x, t = threadIdx.x;   // 128 blocks x 128 thr
    __shared__ float p[64];
    if (t < 64) p[t] = g_pooled[g * HID + t];
    __syncthreads();
    float acc = fc1b[t];
#pragma unroll
    for (int k = 0; k < 64; k++) acc = fmaf(p[k], fc1w[k * DENSE + t], acc);
    float v = fmaxf(acc, 0.f) * fc2w[t];
    __shared__ float sh[128];
    sh[t] = v;
    __syncthreads();
    if (t < 64) sh[t] += sh[t + 64];
    __syncthreads();
    if (t < 32) {
        float s = sh[t] + sh[t + 32];
#pragma unroll
        for (int off = 16; off; off >>= 1) s += __shfl_down_sync(0xffffffffu, s, off);
        if (t == 0) out[g] = s + fc2b[0];
    }
}

// ---------------------------------------------------------------- launch
extern "C" void kernel_launch(void* const* d_in, const int* in_sizes, int n_in,
                              void* d_out, int out_size) {
    const float* x     = (const float*)d_in[0];
    const int*   ei    = (const int*)d_in[1];     // int32 (JAX x64 disabled)
    const int*   batch = (const int*)d_in[2];     // int32
    const float* W0    = (const float*)d_in[3];
    const float* b0    = (const float*)d_in[4];
    const float* W1    = (const float*)d_in[5];
    const float* b1    = (const float*)d_in[6];
    const float* W2    = (const float*)d_in[7];
    const float* b2    = (const float*)d_in[8];
    const float* fc1w  = (const float*)d_in[9];
    const float* fc1b  = (const float*)d_in[10];
    const float* fc2w  = (const float*)d_in[11];
    const float* fc2b  = (const float*)d_in[12];
    float* out = (float*)d_out;

    // CSR build (recomputed every call; deterministic)
    zero_cnt_k<<<(N_NODES + 1023) / 1024, 1024>>>();
    hist_k<<<(N_EDGES + 255) / 256, 256>>>(ei);
    scan_k<<<1, 1024>>>();
    fill_k<<<(N_EDGES + 255) / 256, 256>>>(ei);
    dinv_k<<<(N_NODES + 1023) / 1024, 1024>>>();

    const int AGG_BLOCKS  = (N_NODES * 32 + 255) / 256;   // one warp per node
    const int GEMM_BLOCKS = (N_NODES + 63) / 64;

    // Layer 0
    gemm0_k<<<(N_NODES * 32 + 255) / 256, 256>>>(x, W0);
    agg_k<<<AGG_BLOCKS, 256>>>(b0);
    // Layer 1
    gemm64_k<<<GEMM_BLOCKS, 256>>>(W1);
    agg_k<<<AGG_BLOCKS, 256>>>(b1);
    // Layer 2
    gemm64_k<<<GEMM_BLOCKS, 256>>>(W2);
    agg_k<<<AGG_BLOCKS, 256>>>(b2);

    // Pool + head
    pool_k<<<NGRAPH, 256>>>(batch);
    fc_k<<<NGRAPH, DENSE>>>(fc1w, fc1b, fc2w, fc2b, out);
}

// round 3
// speedup vs baseline: 1.3053x; 1.3053x over previous
#include <cuda_runtime.h>

#define N_NODES 100000
#define N_EDGES 1600000
#define HID 64
#define NGRAPH 128
#define DENSE 128
#define SCAN_BLK 4096
#define NB ((N_NODES + SCAN_BLK - 1) / SCAN_BLK)   // 25

// Scratch
__device__ float  g_buf0[N_NODES * HID];   // h (post-relu conv output / gemm input)
__device__ float  g_buf1[N_NODES * HID];   // g = (h@W)*dinv[row] (gather buffer)
__device__ int    g_cnt[N_NODES];
__device__ int    g_rowptr[N_NODES + 1];
__device__ int    g_cursor[N_NODES];
__device__ int    g_col[N_EDGES];
__device__ float  g_dinv[N_NODES];
__device__ float4 g_xd[N_NODES];           // x * dinv[src], padded
__device__ float4 g_aggx[N_NODES];         // layer-0 aggregated input (3ch)
__device__ int    g_bsum[NB];
__device__ int    g_boff[NB + 1];
__device__ float  g_pooled[NGRAPH * HID];

// ---------------------------------------------------------------- CSR build
__global__ void zero_cnt_k() {
    int i = blockIdx.x * blockDim.x + threadIdx.x;
    int4* p = (int4*)g_cnt;
    if (i < N_NODES / 4) p[i] = make_int4(0, 0, 0, 0);
}

__global__ void hist_k(const int* __restrict__ ei) {
    int i = blockIdx.x * blockDim.x + threadIdx.x;   // 4 edges per thread
    if (i < N_EDGES / 4) {
        int4 d = ((const int4*)(ei + N_EDGES))[i];
        atomicAdd(&g_cnt[d.x], 1);
        atomicAdd(&g_cnt[d.y], 1);
        atomicAdd(&g_cnt[d.z], 1);
        atomicAdd(&g_cnt[d.w], 1);
    }
}

// Per-block local exclusive scan (4096 elems / block), block total to g_bsum.
__global__ void scan1_k() {
    __shared__ int sh[1024];
    int tid = threadIdx.x;
    int base = blockIdx.x * SCAN_BLK;
    int v[4];
    int local = 0;
#pragma unroll
    for (int q = 0; q < 4; q++) {
        int i = base + tid * 4 + q;
        v[q] = (i < N_NODES) ? g_cnt[i] : 0;
        local += v[q];
    }
    sh[tid] = local;
    for (int off = 1; off < 1024; off <<= 1) {
        __syncthreads();
        int t = (tid >= off) ? sh[tid - off] : 0;
        __syncthreads();
        sh[tid] += t;
    }
    __syncthreads();
    int run = sh[tid] - local;   // exclusive for this thread's first item
#pragma unroll
    for (int q = 0; q < 4; q++) {
        int i = base + tid * 4 + q;
        if (i < N_NODES) { g_rowptr[i] = run; run += v[q]; }
    }
    if (tid == 1023) g_bsum[blockIdx.x] = sh[1023];
}

__global__ void scan2_k() {
    if (threadIdx.x == 0) {
        int run = 0;
        for (int b = 0; b < NB; b++) { g_boff[b] = run; run += g_bsum[b]; }
        g_boff[NB] = run;
        g_rowptr[N_NODES] = run;
    }
}

// Add block offsets; init cursor; compute dinv and xd = x*dinv.
__global__ void scan3_k(const float* __restrict__ x) {
    int i = blockIdx.x * blockDim.x + threadIdx.x;
    if (i < N_NODES) {
        int r = g_rowptr[i] + g_boff[i / SCAN_BLK];
        g_rowptr[i] = r;
        g_cursor[i] = r;
        float di = rsqrtf((float)(g_cnt[i] + 1));   // +1 self loop
        g_dinv[i] = di;
        float x0 = x[i * 3 + 0], x1 = x[i * 3 + 1], x2 = x[i * 3 + 2];
        g_xd[i] = make_float4(x0 * di, x1 * di, x2 * di, 0.f);
    }
}

__global__ void fill_k(const int* __restrict__ ei) {
    int i = blockIdx.x * blockDim.x + threadIdx.x;   // 4 edges per thread
    if (i < N_EDGES / 4) {
        int4 s = ((const int4*)ei)[i];
        int4 d = ((const int4*)(ei + N_EDGES))[i];
        g_col[atomicAdd(&g_cursor[d.x], 1)] = s.x;
        g_col[atomicAdd(&g_cursor[d.y], 1)] = s.y;
        g_col[atomicAdd(&g_cursor[d.z], 1)] = s.z;
        g_col[atomicAdd(&g_cursor[d.w], 1)] = s.w;
    }
}

// ---------------------------------------------------------------- Layer 0
// agg_x: a[i] = dinv[i] * (xd[i] + sum_{src in N(i)} xd[src])  (3 channels)
__global__ void agg_x_k() {
    int w    = (blockIdx.x * blockDim.x + threadIdx.x) >> 5;
    int lane = threadIdx.x & 31;
    if (w >= N_NODES) return;
    int s = g_rowptr[w];
    int e = g_rowptr[w + 1];
    float4 acc = (lane == 0) ? g_xd[w] : make_float4(0.f, 0.f, 0.f, 0.f);
    for (int idx = s + lane; idx < e; idx += 32) {
        float4 v = g_xd[g_col[idx]];
        acc.x += v.x; acc.y += v.y; acc.z += v.z;
    }
#pragma unroll
    for (int off = 16; off; off >>= 1) {
        acc.x += __shfl_xor_sync(0xffffffffu, acc.x, off);
        acc.y += __shfl_xor_sync(0xffffffffu, acc.y, off);
        acc.z += __shfl_xor_sync(0xffffffffu, acc.z, off);
    }
    if (lane == 0) {
        float di = g_dinv[w];
        g_aggx[w] = make_float4(acc.x * di, acc.y * di, acc.z * di, 0.f);
    }
}

// gemm0: h0 = relu(aggx @ W0 + b0) -> g_buf0
__global__ void gemm0_k(const float* __restrict__ W0, const float* __restrict__ b0) {
    __shared__ float Ws[3 * HID];
    __shared__ float Bs[HID];
    int t = threadIdx.x;
    if (t < 3 * HID) Ws[t] = W0[t];
    if (t < HID) Bs[t] = b0[t];
    __syncthreads();
    int idx = blockIdx.x * blockDim.x + t;   // thread per (row, channel-pair)
    int row = idx >> 5;
    int cp  = (idx & 31) * 2;
    if (row < N_NODES) {
        float4 a = g_aggx[row];
        float v0 = fmaf(a.x, Ws[cp],     fmaf(a.y, Ws[HID + cp],     a.z * Ws[2 * HID + cp]))     + Bs[cp];
        float v1 = fmaf(a.x, Ws[cp + 1], fmaf(a.y, Ws[HID + cp + 1], a.z * Ws[2 * HID + cp + 1])) + Bs[cp + 1];
        *(float2*)&g_buf0[row * HID + cp] = make_float2(fmaxf(v0, 0.f), fmaxf(v1, 0.f));
    }
}

// ---------------------------------------------------------------- GEMM 64x64
// g_buf1[r] = (g_buf0 @ W)[r] * dinv[r]
__global__ void gemm64_k(const float* __restrict__ W) {
    __shared__ float hs[64 * 65];
    __shared__ float ws[64 * 64];
    int t  = threadIdx.x;
    int rb = blockIdx.x * 64;
    {
        const float4* Wv = (const float4*)W;
        float4* wv = (float4*)ws;
#pragma unroll
        for (int q = 0; q < 4; q++) { int i = t + q * 256; wv[i] = Wv[i]; }
    }
#pragma unroll
    for (int q = 0; q < 4; q++) {
        int i = t + q * 256;
        int r = i >> 4, kq = (i & 15) << 2;
        float4 v = make_float4(0.f, 0.f, 0.f, 0.f);
        if (rb + r < N_NODES) v = *(const float4*)&g_buf0[(rb + r) * HID + kq];
        hs[r * 65 + kq]     = v.x;
        hs[r * 65 + kq + 1] = v.y;
        hs[r * 65 + kq + 2] = v.z;
        hs[r * 65 + kq + 3] = v.w;
    }
    __syncthreads();
    int tx = t & 15, ty = t >> 4;
    int c0 = tx * 4, r0 = ty * 4;
    float acc[4][4] = {};
#pragma unroll
    for (int k = 0; k < 64; k++) {
        float4 b = *(const float4*)&ws[k * 64 + c0];
        float a0 = hs[(r0 + 0) * 65 + k];
        float a1 = hs[(r0 + 1) * 65 + k];
        float a2 = hs[(r0 + 2) * 65 + k];
        float a3 = hs[(r0 + 3) * 65 + k];
        acc[0][0] += a0 * b.x; acc[0][1] += a0 * b.y; acc[0][2] += a0 * b.z; acc[0][3] += a0 * b.w;
        acc[1][0] += a1 * b.x; acc[1][1] += a1 * b.y; acc[1][2] += a1 * b.z; acc[1][3] += a1 * b.w;
        acc[2][0] += a2 * b.x; acc[2][1] += a2 * b.y; acc[2][2] += a2 * b.z; acc[2][3] += a2 * b.w;
        acc[3][0] += a3 * b.x; acc[3][1] += a3 * b.y; acc[3][2] += a3 * b.z; acc[3][3] += a3 * b.w;
    }
#pragma unroll
    for (int i = 0; i < 4; i++) {
        int r = rb + r0 + i;
        if (r < N_NODES) {
            float di = g_dinv[r];
            *(float4*)&g_buf1[r * HID + c0] =
                make_float4(acc[i][0] * di, acc[i][1] * di, acc[i][2] * di, acc[i][3] * di);
        }
    }
}

// ---------------------------------------------------------------- Aggregation
// One warp per dst node; 2 half-warps process 2 edges at once, float4/lane.
// out[i] = relu(dinv[i] * (g[i] + sum_{src} g[src]) + bias)
__global__ void agg_k(const float* __restrict__ bias) {
    int w    = (blockIdx.x * blockDim.x + threadIdx.x) >> 5;
    int lane = threadIdx.x & 31;
    if (w >= N_NODES) return;
    int half = lane >> 4;
    int c4   = (lane & 15) * 4;
    int s = g_rowptr[w];
    int e = g_rowptr[w + 1];
    float4 acc0 = make_float4(0.f, 0.f, 0.f, 0.f);
    float4 acc1 = make_float4(0.f, 0.f, 0.f, 0.f);
    for (int base = s; base < e; base += 32) {
        int idx = base + lane;
        int cv = (idx < e) ? g_col[idx] : 0;
        int m = e - base;
        if (m > 32) m = 32;
        int j = 0;
        for (; j + 4 <= m; j += 4) {
            int s0 = __shfl_sync(0xffffffffu, cv, j + half);
            int s1 = __shfl_sync(0xffffffffu, cv, j + 2 + half);
            float4 v0 = *(const float4*)&g_buf1[s0 * HID + c4];
            float4 v1 = *(const float4*)&g_buf1[s1 * HID + c4];
            acc0.x += v0.x; acc0.y += v0.y; acc0.z += v0.z; acc0.w += v0.w;
            acc1.x += v1.x; acc1.y += v1.y; acc1.z += v1.z; acc1.w += v1.w;
        }
        for (; j < m; j += 2) {
            int jj = j + half;
            int sj = __shfl_sync(0xffffffffu, cv, (jj < m) ? jj : (m - 1));
            if (jj < m) {
                float4 v = *(const float4*)&g_buf1[sj * HID + c4];
                acc0.x += v.x; acc0.y += v.y; acc0.z += v.z; acc0.w += v.w;
            }
        }
    }
    acc0.x += acc1.x; acc0.y += acc1.y; acc0.z += acc1.z; acc0.w += acc1.w;
    // merge the two half-warps (channels match between lane and lane^16)
    acc0.x += __shfl_xor_sync(0xffffffffu, acc0.x, 16);
    acc0.y += __shfl_xor_sync(0xffffffffu, acc0.y, 16);
    acc0.z += __shfl_xor_sync(0xffffffffu, acc0.z, 16);
    acc0.w += __shfl_xor_sync(0xffffffffu, acc0.w, 16);
    if (half == 0) {
        float4 self = *(const float4*)&g_buf1[w * HID + c4];
        float4 bb   = *(const float4*)&bias[c4];
        float di = g_dinv[w];
        float4 r;
        r.x = fmaxf(fmaf(acc0.x + self.x, di, bb.x), 0.f);
        r.y = fmaxf(fmaf(acc0.y + self.y, di, bb.y), 0.f);
        r.z = fmaxf(fmaf(acc0.z + self.z, di, bb.z), 0.f);
        r.w = fmaxf(fmaf(acc0.w + self.w, di, bb.w), 0.f);
        *(float4*)&g_buf0[w * HID + c4] = r;
    }
}

// ---------------------------------------------------------------- Pool + head
__global__ void pool_k(const int* __restrict__ batch) {
    int g = blockIdx.x, t = threadIdx.x;   // 128 blocks x 256 thr
    __shared__ int lo_s, hi_s;
    if (t == 0) {
        int lo = 0, hi = N_NODES;
        while (lo < hi) { int m = (lo + hi) >> 1; if (batch[m] < g) lo = m + 1; else hi = m; }
        lo_s = lo;
        int lo2 = lo, hi2 = N_NODES;
        while (lo2 < hi2) { int m = (lo2 + hi2) >> 1; if (batch[m] < g + 1) lo2 = m + 1; else hi2 = m; }
        hi_s = lo2;
    }
    __syncthreads();
    int lo = lo_s, hi = hi_s;
    int c = t & 63, rg = t >> 6;
    float acc = 0.f;
    for (int r = lo + rg; r < hi; r += 4) acc += g_buf0[r * HID + c];
    __shared__ float sh[256];
    sh[t] = acc;
    __syncthreads();
    if (t < 64) {
        float s = sh[t] + sh[t + 64] + sh[t + 128] + sh[t + 192];
        float cntf = (float)(hi - lo);
        if (cntf < 1.f) cntf = 1.f;
        g_pooled[g * HID + t] = s / cntf;
    }
}

__global__ void fc_k(const float* __restrict__ fc1w, const float* __restrict__ fc1b,
                     const float* __restrict__ fc2w, const float* __restrict__ fc2b,
                     float* __restrict__ out) {
    int g = blockIdx.x, t = threadIdx.x;   // 128 blocks x 128 thr
    __shared__ float p[64];
    if (t < 64) p[t] = g_pooled[g * HID + t];
    __syncthreads();
    float acc = fc1b[t];
#pragma unroll
    for (int k = 0; k < 64; k++) acc = fmaf(p[k], fc1w[k * DENSE + t], acc);
    float v = fmaxf(acc, 0.f) * fc2w[t];
    __shared__ float sh[128];
    sh[t] = v;
    __syncthreads();
    if (t < 64) sh[t] += sh[t + 64];
    __syncthreads();
    if (t < 32) {
        float s = sh[t] + sh[t + 32];
#pragma unroll
        for (int off = 16; off; off >>= 1) s += __shfl_down_sync(0xffffffffu, s, off);
        if (t == 0) out[g] = s + fc2b[0];
    }
}

// ---------------------------------------------------------------- launch
extern "C" void kernel_launch(void* const* d_in, const int* in_sizes, int n_in,
                              void* d_out, int out_size) {
    const float* x     = (const float*)d_in[0];
    const int*   ei    = (const int*)d_in[1];
    const int*   batch = (const int*)d_in[2];
    const float* W0    = (const float*)d_in[3];
    const float* b0    = (const float*)d_in[4];
    const float* W1    = (const float*)d_in[5];
    const float* b1    = (const float*)d_in[6];
    const float* W2    = (const float*)d_in[7];
    const float* b2    = (const float*)d_in[8];
    const float* fc1w  = (const float*)d_in[9];
    const float* fc1b  = (const float*)d_in[10];
    const float* fc2w  = (const float*)d_in[11];
    const float* fc2b  = (const float*)d_in[12];
    float* out = (float*)d_out;

    // CSR build
    zero_cnt_k<<<(N_NODES / 4 + 255) / 256, 256>>>();
    hist_k<<<(N_EDGES / 4 + 255) / 256, 256>>>(ei);
    scan1_k<<<NB, 1024>>>();
    scan2_k<<<1, 32>>>();
    scan3_k<<<(N_NODES + 255) / 256, 256>>>(x);
    fill_k<<<(N_EDGES / 4 + 255) / 256, 256>>>(ei);

    const int AGG_BLOCKS  = (N_NODES * 32 + 255) / 256;
    const int GEMM_BLOCKS = (N_NODES + 63) / 64;

    // Layer 0 (aggregate in 3-channel input space, then dense)
    agg_x_k<<<AGG_BLOCKS, 256>>>();
    gemm0_k<<<(N_NODES * 32 + 255) / 256, 256>>>(W0, b0);
    // Layer 1
    gemm64_k<<<GEMM_BLOCKS, 256>>>(W1);
    agg_k<<<AGG_BLOCKS, 256>>>(b1);
    // Layer 2
    gemm64_k<<<GEMM_BLOCKS, 256>>>(W2);
    agg_k<<<AGG_BLOCKS, 256>>>(b2);

    // Pool + head
    pool_k<<<NGRAPH, 256>>>(batch);
    fc_k<<<NGRAPH, DENSE>>>(fc1w, fc1b, fc2w, fc2b, out);
}

// round 4
// speedup vs baseline: 1.5245x; 1.1680x over previous
#include <cuda_runtime.h>
#include <cuda_bf16.h>

#define N_NODES 100000
#define N_EDGES 1600000
#define HID 64
#define NGRAPH 128
#define DENSE 128
#define SCAN_BLK 4096
#define NB ((N_NODES + SCAN_BLK - 1) / SCAN_BLK)   // 25

// Scratch
__device__ float           g_buf0[N_NODES * HID];  // h (post-relu, fp32 gemm input)
__device__ __nv_bfloat16   g_gath[N_NODES * HID];  // (h@W)*dinv, bf16 gather buffer
__device__ int    g_cnt[N_NODES];
__device__ int    g_rowptr[N_NODES + 1];
__device__ int    g_cursor[N_NODES];
__device__ int    g_col[N_EDGES];
__device__ float  g_dinv[N_NODES];
__device__ float4 g_xd[N_NODES];           // x * dinv[src], padded
__device__ float4 g_aggx[N_NODES];         // layer-0 aggregated input (3ch)
__device__ int    g_bsum[NB];
__device__ int    g_boff[NB + 1];
__device__ float  g_pooled[NGRAPH * HID];

// ---------------------------------------------------------------- CSR build
__global__ void hist_k(const int* __restrict__ ei) {
    int i = blockIdx.x * blockDim.x + threadIdx.x;   // 4 edges per thread
    if (i < N_EDGES / 4) {
        int4 d = ((const int4*)(ei + N_EDGES))[i];
        atomicAdd(&g_cnt[d.x], 1);
        atomicAdd(&g_cnt[d.y], 1);
        atomicAdd(&g_cnt[d.z], 1);
        atomicAdd(&g_cnt[d.w], 1);
    }
}

// Per-block local exclusive scan (4096 elems / block), block total to g_bsum.
__global__ void scan1_k() {
    __shared__ int sh[1024];
    int tid = threadIdx.x;
    int base = blockIdx.x * SCAN_BLK;
    int v[4];
    int local = 0;
#pragma unroll
    for (int q = 0; q < 4; q++) {
        int i = base + tid * 4 + q;
        v[q] = (i < N_NODES) ? g_cnt[i] : 0;
        local += v[q];
    }
    sh[tid] = local;
    for (int off = 1; off < 1024; off <<= 1) {
        __syncthreads();
        int t = (tid >= off) ? sh[tid - off] : 0;
        __syncthreads();
        sh[tid] += t;
    }
    __syncthreads();
    int run = sh[tid] - local;
#pragma unroll
    for (int q = 0; q < 4; q++) {
        int i = base + tid * 4 + q;
        if (i < N_NODES) { g_rowptr[i] = run; run += v[q]; }
    }
    if (tid == 1023) g_bsum[blockIdx.x] = sh[1023];
}

// Warp-shuffle scan over NB block sums.
__global__ void scan2_k() {
    int t = threadIdx.x;             // 32 threads
    int v = (t < NB) ? g_bsum[t] : 0;
    int incl = v;
#pragma unroll
    for (int off = 1; off < 32; off <<= 1) {
        int u = __shfl_up_sync(0xffffffffu, incl, off);
        if (t >= off) incl += u;
    }
    if (t < NB) g_boff[t] = incl - v;
    int total = __shfl_sync(0xffffffffu, incl, 31);
    if (t == 0) { g_boff[NB] = total; g_rowptr[N_NODES] = total; }
}

// Add block offsets; init cursor; compute dinv and xd = x*dinv.
__global__ void scan3_k(const float* __restrict__ x) {
    int i = blockIdx.x * blockDim.x + threadIdx.x;
    if (i < N_NODES) {
        int r = g_rowptr[i] + g_boff[i / SCAN_BLK];
        g_rowptr[i] = r;
        g_cursor[i] = r;
        float di = rsqrtf((float)(g_cnt[i] + 1));   // +1 self loop
        g_dinv[i] = di;
        float x0 = x[i * 3 + 0], x1 = x[i * 3 + 1], x2 = x[i * 3 + 2];
        g_xd[i] = make_float4(x0 * di, x1 * di, x2 * di, 0.f);
    }
}

__global__ void fill_k(const int* __restrict__ ei) {
    int i = blockIdx.x * blockDim.x + threadIdx.x;   // 4 edges per thread
    if (i < N_EDGES / 4) {
        int4 s = ((const int4*)ei)[i];
        int4 d = ((const int4*)(ei + N_EDGES))[i];
        g_col[atomicAdd(&g_cursor[d.x], 1)] = s.x;
        g_col[atomicAdd(&g_cursor[d.y], 1)] = s.y;
        g_col[atomicAdd(&g_cursor[d.z], 1)] = s.z;
        g_col[atomicAdd(&g_cursor[d.w], 1)] = s.w;
    }
}

// ---------------------------------------------------------------- Layer 0
__global__ void agg_x_k() {
    int w    = (blockIdx.x * blockDim.x + threadIdx.x) >> 5;
    int lane = threadIdx.x & 31;
    if (w >= N_NODES) return;
    int s = g_rowptr[w];
    int e = g_rowptr[w + 1];
    float4 acc = (lane == 0) ? g_xd[w] : make_float4(0.f, 0.f, 0.f, 0.f);
    for (int idx = s + lane; idx < e; idx += 32) {
        float4 v = g_xd[g_col[idx]];
        acc.x += v.x; acc.y += v.y; acc.z += v.z;
    }
#pragma unroll
    for (int off = 16; off; off >>= 1) {
        acc.x += __shfl_xor_sync(0xffffffffu, acc.x, off);
        acc.y += __shfl_xor_sync(0xffffffffu, acc.y, off);
        acc.z += __shfl_xor_sync(0xffffffffu, acc.z, off);
    }
    if (lane == 0) {
        float di = g_dinv[w];
        g_aggx[w] = make_float4(acc.x * di, acc.y * di, acc.z * di, 0.f);
    }
}

// gemm0: h0 = relu(aggx @ W0 + b0) -> g_buf0 (fp32)
__global__ void gemm0_k(const float* __restrict__ W0, const float* __restrict__ b0) {
    __shared__ float Ws[3 * HID];
    __shared__ float Bs[HID];
    int t = threadIdx.x;
    if (t < 3 * HID) Ws[t] = W0[t];
    if (t < HID) Bs[t] = b0[t];
    __syncthreads();
    int idx = blockIdx.x * blockDim.x + t;
    int row = idx >> 5;
    int cp  = (idx & 31) * 2;
    if (row < N_NODES) {
        float4 a = g_aggx[row];
        float v0 = fmaf(a.x, Ws[cp],     fmaf(a.y, Ws[HID + cp],     a.z * Ws[2 * HID + cp]))     + Bs[cp];
        float v1 = fmaf(a.x, Ws[cp + 1], fmaf(a.y, Ws[HID + cp + 1], a.z * Ws[2 * HID + cp + 1])) + Bs[cp + 1];
        *(float2*)&g_buf0[row * HID + cp] = make_float2(fmaxf(v0, 0.f), fmaxf(v1, 0.f));
    }
}

// ---------------------------------------------------------------- GEMM 64x64
// g_gath[r] = bf16( (g_buf0 @ W)[r] * dinv[r] )
__global__ void gemm64_k(const float* __restrict__ W) {
    __shared__ float hs[64 * 65];
    __shared__ float ws[64 * 64];
    int t  = threadIdx.x;
    int rb = blockIdx.x * 64;
    {
        const float4* Wv = (const float4*)W;
        float4* wv = (float4*)ws;
#pragma unroll
        for (int q = 0; q < 4; q++) { int i = t + q * 256; wv[i] = Wv[i]; }
    }
#pragma unroll
    for (int q = 0; q < 4; q++) {
        int i = t + q * 256;
        int r = i >> 4, kq = (i & 15) << 2;
        float4 v = make_float4(0.f, 0.f, 0.f, 0.f);
        if (rb + r < N_NODES) v = *(const float4*)&g_buf0[(rb + r) * HID + kq];
        hs[r * 65 + kq]     = v.x;
        hs[r * 65 + kq + 1] = v.y;
        hs[r * 65 + kq + 2] = v.z;
        hs[r * 65 + kq + 3] = v.w;
    }
    __syncthreads();
    int tx = t & 15, ty = t >> 4;
    int c0 = tx * 4, r0 = ty * 4;
    float acc[4][4] = {};
#pragma unroll
    for (int k = 0; k < 64; k++) {
        float4 b = *(const float4*)&ws[k * 64 + c0];
        float a0 = hs[(r0 + 0) * 65 + k];
        float a1 = hs[(r0 + 1) * 65 + k];
        float a2 = hs[(r0 + 2) * 65 + k];
        float a3 = hs[(r0 + 3) * 65 + k];
        acc[0][0] += a0 * b.x; acc[0][1] += a0 * b.y; acc[0][2] += a0 * b.z; acc[0][3] += a0 * b.w;
        acc[1][0] += a1 * b.x; acc[1][1] += a1 * b.y; acc[1][2] += a1 * b.z; acc[1][3] += a1 * b.w;
        acc[2][0] += a2 * b.x; acc[2][1] += a2 * b.y; acc[2][2] += a2 * b.z; acc[2][3] += a2 * b.w;
        acc[3][0] += a3 * b.x; acc[3][1] += a3 * b.y; acc[3][2] += a3 * b.z; acc[3][3] += a3 * b.w;
    }
#pragma unroll
    for (int i = 0; i < 4; i++) {
        int r = rb + r0 + i;
        if (r < N_NODES) {
            float di = g_dinv[r];
            __nv_bfloat162 p0 = __floats2bfloat162_rn(acc[i][0] * di, acc[i][1] * di);
            __nv_bfloat162 p1 = __floats2bfloat162_rn(acc[i][2] * di, acc[i][3] * di);
            uint2 pk;
            pk.x = *(unsigned int*)&p0;
            pk.y = *(unsigned int*)&p1;
            *(uint2*)&g_gath[r * HID + c0] = pk;
        }
    }
}

// ---------------------------------------------------------------- Aggregation
// One warp per dst node; 4 groups x 8 lanes. Each lane: 8 channels (uint4 of bf16),
// each group one edge; 8 edges in flight per iteration. fp32 accumulate.
// out[i] = relu(dinv[i] * (g[i] + sum_{src} g[src]) + bias)  -> g_buf0 fp32
__global__ void agg_k(const float* __restrict__ bias) {
    int w    = (blockIdx.x * blockDim.x + threadIdx.x) >> 5;
    int lane = threadIdx.x & 31;
    if (w >= N_NODES) return;
    int grp = lane >> 3;          // 0..3
    int l8  = lane & 7;           // 0..7
    int ch0 = l8 * 8;             // first of 8 channels for this lane
    int s = g_rowptr[w];
    int e = g_rowptr[w + 1];

    float2 a0 = make_float2(0.f, 0.f), a1 = a0, a2 = a0, a3 = a0;

#define ACC_ROW(SRC)                                                          \
    {                                                                         \
        uint4 pk = *(const uint4*)&g_gath[(SRC) * HID + ch0];                 \
        float2 f0 = __bfloat1622float2(*(__nv_bfloat162*)&pk.x);              \
        float2 f1 = __bfloat1622float2(*(__nv_bfloat162*)&pk.y);              \
        float2 f2 = __bfloat1622float2(*(__nv_bfloat162*)&pk.z);              \
        float2 f3 = __bfloat1622float2(*(__nv_bfloat162*)&pk.w);              \
        a0.x += f0.x; a0.y += f0.y; a1.x += f1.x; a1.y += f1.y;               \
        a2.x += f2.x; a2.y += f2.y; a3.x += f3.x; a3.y += f3.y;               \
    }

    for (int base = s; base < e; base += 32) {
        int idx = base + lane;
        int cv = (idx < e) ? g_col[idx] : 0;
        int m = e - base;
        if (m > 32) m = 32;
        int j = 0;
        for (; j + 8 <= m; j += 8) {
            int s0 = __shfl_sync(0xffffffffu, cv, j + grp);
            int s1 = __shfl_sync(0xffffffffu, cv, j + 4 + grp);
            ACC_ROW(s0);
            ACC_ROW(s1);
        }
        for (; j < m; j += 4) {
            int jj = j + grp;
            int sj = __shfl_sync(0xffffffffu, cv, (jj < m) ? jj : (m - 1));
            if (jj < m) ACC_ROW(sj);
        }
    }
#undef ACC_ROW

    // reduce across the 4 groups (lanes with equal l8)
#pragma unroll
    for (int off = 8; off <= 16; off <<= 1) {
        a0.x += __shfl_xor_sync(0xffffffffu, a0.x, off);
        a0.y += __shfl_xor_sync(0xffffffffu, a0.y, off);
        a1.x += __shfl_xor_sync(0xffffffffu, a1.x, off);
        a1.y += __shfl_xor_sync(0xffffffffu, a1.y, off);
        a2.x += __shfl_xor_sync(0xffffffffu, a2.x, off);
        a2.y += __shfl_xor_sync(0xffffffffu, a2.y, off);
        a3.x += __shfl_xor_sync(0xffffffffu, a3.x, off);
        a3.y += __shfl_xor_sync(0xffffffffu, a3.y, off);
    }

    if (grp == 0) {
        // self loop
        uint4 pk = *(const uint4*)&g_gath[w * HID + ch0];
        float2 f0 = __bfloat1622float2(*(__nv_bfloat162*)&pk.x);
        float2 f1 = __bfloat1622float2(*(__nv_bfloat162*)&pk.y);
        float2 f2 = __bfloat1622float2(*(__nv_bfloat162*)&pk.z);
        float2 f3 = __bfloat1622float2(*(__nv_bfloat162*)&pk.w);
        a0.x += f0.x; a0.y += f0.y; a1.x += f1.x; a1.y += f1.y;
        a2.x += f2.x; a2.y += f2.y; a3.x += f3.x; a3.y += f3.y;

        float di = g_dinv[w];
        float4 bA = *(const float4*)&bias[ch0];
        float4 bB = *(const float4*)&bias[ch0 + 4];
        float4 r0, r1;
        r0.x = fmaxf(fmaf(a0.x, di, bA.x), 0.f);
        r0.y = fmaxf(fmaf(a0.y, di, bA.y), 0.f);
        r0.z = fmaxf(fmaf(a1.x, di, bA.z), 0.f);
        r0.w = fmaxf(fmaf(a1.y, di, bA.w), 0.f);
        r1.x = fmaxf(fmaf(a2.x, di, bB.x), 0.f);
        r1.y = fmaxf(fmaf(a2.y, di, bB.y), 0.f);
        r1.z = fmaxf(fmaf(a3.x, di, bB.z), 0.f);
        r1.w = fmaxf(fmaf(a3.y, di, bB.w), 0.f);
        *(float4*)&g_buf0[w * HID + ch0]     = r0;
        *(float4*)&g_buf0[w * HID + ch0 + 4] = r1;
    }
}

// ---------------------------------------------------------------- Pool + head
__global__ void pool_k(const int* __restrict__ batch) {
    int g = blockIdx.x, t = threadIdx.x;   // 128 blocks x 256 thr
    __shared__ int lo_s, hi_s;
    if (t == 0) {
        int lo = 0, hi = N_NODES;
        while (lo < hi) { int m = (lo + hi) >> 1; if (batch[m] < g) lo = m + 1; else hi = m; }
        lo_s = lo;
        int lo2 = lo, hi2 = N_NODES;
        while (lo2 < hi2) { int m = (lo2 + hi2) >> 1; if (batch[m] < g + 1) lo2 = m + 1; else hi2 = m; }
        hi_s = lo2;
    }
    __syncthreads();
    int lo = lo_s, hi = hi_s;
    int c = t & 63, rg = t >> 6;
    float acc = 0.f;
    for (int r = lo + rg; r < hi; r += 4) acc += g_buf0[r * HID + c];
    __shared__ float sh[256];
    sh[t] = acc;
    __syncthreads();
    if (t < 64) {
        float s = sh[t] + sh[t + 64] + sh[t + 128] + sh[t + 192];
        float cntf = (float)(hi - lo);
        if (cntf < 1.f) cntf = 1.f;
        g_pooled[g * HID + t] = s / cntf;
    }
}

__global__ void fc_k(const float* __restrict__ fc1w, const float* __restrict__ fc1b,
                     const float* __restrict__ fc2w, const float* __restrict__ fc2b,
                     float* __restrict__ out) {
    int g = blockIdx.x, t = threadIdx.x;   // 128 blocks x 128 thr
    __shared__ float p[64];
    if (t < 64) p[t] = g_pooled[g * HID + t];
    __syncthreads();
    float acc = fc1b[t];
#pragma unroll
    for (int k = 0; k < 64; k++) acc = fmaf(p[k], fc1w[k * DENSE + t], acc);
    float v = fmaxf(acc, 0.f) * fc2w[t];
    __shared__ float sh[128];
    sh[t] = v;
    __syncthreads();
    if (t < 64) sh[t] += sh[t + 64];
    __syncthreads();
    if (t < 32) {
        float s = sh[t] + sh[t + 32];
#pragma unroll
        for (int off = 16; off; off >>= 1) s += __shfl_down_sync(0xffffffffu, s, off);
        if (t == 0) out[g] = s + fc2b[0];
    }
}

// ---------------------------------------------------------------- launch
extern "C" void kernel_launch(void* const* d_in, const int* in_sizes, int n_in,
                              void* d_out, int out_size) {
    const float* x     = (const float*)d_in[0];
    const int*   ei    = (const int*)d_in[1];
    const int*   batch = (const int*)d_in[2];
    const float* W0    = (const float*)d_in[3];
    const float* b0    = (const float*)d_in[4];
    const float* W1    = (const float*)d_in[5];
    const float* b1    = (const float*)d_in[6];
    const float* W2    = (const float*)d_in[7];
    const float* b2    = (const float*)d_in[8];
    const float* fc1w  = (const float*)d_in[9];
    const float* fc1b  = (const float*)d_in[10];
    const float* fc2w  = (const float*)d_in[11];
    const float* fc2b  = (const float*)d_in[12];
    float* out = (float*)d_out;

    // CSR build
    void* cnt_ptr = nullptr;
    cudaGetSymbolAddress(&cnt_ptr, g_cnt);
    cudaMemsetAsync(cnt_ptr, 0, N_NODES * sizeof(int));
    hist_k<<<(N_EDGES / 4 + 255) / 256, 256>>>(ei);
    scan1_k<<<NB, 1024>>>();
    scan2_k<<<1, 32>>>();
    scan3_k<<<(N_NODES + 255) / 256, 256>>>(x);
    fill_k<<<(N_EDGES / 4 + 255) / 256, 256>>>(ei);

    const int AGG_BLOCKS  = (N_NODES * 32 + 255) / 256;
    const int GEMM_BLOCKS = (N_NODES + 63) / 64;

    // Layer 0 (aggregate in 3-channel input space, then dense)
    agg_x_k<<<AGG_BLOCKS, 256>>>();
    gemm0_k<<<(N_NODES * 32 + 255) / 256, 256>>>(W0, b0);
    // Layer 1
    gemm64_k<<<GEMM_BLOCKS, 256>>>(W1);
    agg_k<<<AGG_BLOCKS, 256>>>(b1);
    // Layer 2
    gemm64_k<<<GEMM_BLOCKS, 256>>>(W2);
    agg_k<<<AGG_BLOCKS, 256>>>(b2);

    // Pool + head
    pool_k<<<NGRAPH, 256>>>(batch);
    fc_k<<<NGRAPH, DENSE>>>(fc1w, fc1b, fc2w, fc2b, out);
}

// round 5
// speedup vs baseline: 1.6211x; 1.0633x over previous
#include <cuda_runtime.h>
#include <cuda_bf16.h>

#define N_NODES 100000
#define N_EDGES 1600000
#define HID 64
#define NGRAPH 128
#define DENSE 128
#define SCAN_BLK 4096
#define NB ((N_NODES + SCAN_BLK - 1) / SCAN_BLK)   // 25

// Scratch
__device__ float           g_buf0[N_NODES * HID];  // h (post-relu, fp32 gemm input)
__device__ __nv_bfloat16   g_gath[N_NODES * HID];  // (h@W)*dinv, bf16 gather buffer
__device__ int    g_cnt[N_NODES];
__device__ int    g_rowptr[N_NODES + 1];
__device__ int    g_cursor[N_NODES];
__device__ int    g_col[N_EDGES];
__device__ float  g_dinv[N_NODES];
__device__ float4 g_xd[N_NODES];           // x * dinv[src], padded
__device__ int    g_bsum[NB];
__device__ float  g_pooled[NGRAPH * HID];

// ---------------------------------------------------------------- CSR build
__global__ void hist_k(const int* __restrict__ ei) {
    int i = blockIdx.x * blockDim.x + threadIdx.x;   // 4 edges per thread
    if (i < N_EDGES / 4) {
        int4 d = ((const int4*)(ei + N_EDGES))[i];
        atomicAdd(&g_cnt[d.x], 1);
        atomicAdd(&g_cnt[d.y], 1);
        atomicAdd(&g_cnt[d.z], 1);
        atomicAdd(&g_cnt[d.w], 1);
    }
}

// Per-block local exclusive scan (4096 elems / block), block total to g_bsum.
__global__ void scan1_k() {
    __shared__ int sh[1024];
    int tid = threadIdx.x;
    int base = blockIdx.x * SCAN_BLK;
    int v[4];
    int local = 0;
#pragma unroll
    for (int q = 0; q < 4; q++) {
        int i = base + tid * 4 + q;
        v[q] = (i < N_NODES) ? g_cnt[i] : 0;
        local += v[q];
    }
    sh[tid] = local;
    for (int off = 1; off < 1024; off <<= 1) {
        __syncthreads();
        int t = (tid >= off) ? sh[tid - off] : 0;
        __syncthreads();
        sh[tid] += t;
    }
    __syncthreads();
    int run = sh[tid] - local;
#pragma unroll
    for (int q = 0; q < 4; q++) {
        int i = base + tid * 4 + q;
        if (i < N_NODES) { g_rowptr[i] = run; run += v[q]; }
    }
    if (tid == 1023) g_bsum[blockIdx.x] = sh[1023];
}

// Add block offsets (computed redundantly per block from g_bsum);
// init cursor; compute dinv and xd = x*dinv.
__global__ void scan3_k(const float* __restrict__ x) {
    __shared__ int off_s;
    __shared__ int tot_s;
    int t = threadIdx.x;
    if (t < 32) {
        int myblk = (blockIdx.x * blockDim.x) / SCAN_BLK;  // 256-thr blocks never straddle
        int v = (t < NB) ? g_bsum[t] : 0;
        int pre = (t < myblk) ? v : 0;
        int tot = v;
#pragma unroll
        for (int o = 16; o; o >>= 1) {
            pre += __shfl_xor_sync(0xffffffffu, pre, o);
            tot += __shfl_xor_sync(0xffffffffu, tot, o);
        }
        if (t == 0) { off_s = pre; tot_s = tot; }
    }
    __syncthreads();
    int i = blockIdx.x * blockDim.x + t;
    if (i < N_NODES) {
        int r = g_rowptr[i] + off_s;
        g_rowptr[i] = r;
        g_cursor[i] = r;
        float di = rsqrtf((float)(g_cnt[i] + 1));   // +1 self loop
        g_dinv[i] = di;
        float x0 = x[i * 3 + 0], x1 = x[i * 3 + 1], x2 = x[i * 3 + 2];
        g_xd[i] = make_float4(x0 * di, x1 * di, x2 * di, 0.f);
    }
    if (blockIdx.x == 0 && t == 0) g_rowptr[N_NODES] = tot_s;
}

__global__ void fill_k(const int* __restrict__ ei) {
    int i = blockIdx.x * blockDim.x + threadIdx.x;   // 4 edges per thread
    if (i < N_EDGES / 4) {
        int4 s = ((const int4*)ei)[i];
        int4 d = ((const int4*)(ei + N_EDGES))[i];
        g_col[atomicAdd(&g_cursor[d.x], 1)] = s.x;
        g_col[atomicAdd(&g_cursor[d.y], 1)] = s.y;
        g_col[atomicAdd(&g_cursor[d.z], 1)] = s.z;
        g_col[atomicAdd(&g_cursor[d.w], 1)] = s.w;
    }
}

// ---------------------------------------------------------------- Layer 0 (fused)
// 8 lanes per node: gather-reduce xd (3ch), then each lane emits 8 channels of
// relu(aggx @ W0 + b0) into g_buf0.
__global__ void agg_x_gemm0_k(const float* __restrict__ W0, const float* __restrict__ b0) {
    __shared__ float Ws[3 * HID];
    __shared__ float Bs[HID];
    int t = threadIdx.x;
    if (t < 3 * HID) Ws[t] = W0[t];
    if (t < HID) Bs[t] = b0[t];
    __syncthreads();
    int node = (blockIdx.x * blockDim.x + t) >> 3;
    int l8   = t & 7;
    if (node >= N_NODES) return;
    int s = g_rowptr[node];
    int e = g_rowptr[node + 1];
    float ax = 0.f, ay = 0.f, az = 0.f;
    if (l8 == 0) { float4 v = g_xd[node]; ax = v.x; ay = v.y; az = v.z; }
    for (int idx = s + l8; idx < e; idx += 8) {
        float4 v = g_xd[g_col[idx]];
        ax += v.x; ay += v.y; az += v.z;
    }
#pragma unroll
    for (int off = 1; off < 8; off <<= 1) {
        ax += __shfl_xor_sync(0xffffffffu, ax, off);
        ay += __shfl_xor_sync(0xffffffffu, ay, off);
        az += __shfl_xor_sync(0xffffffffu, az, off);
    }
    float di = g_dinv[node];
    ax *= di; ay *= di; az *= di;
    int c0 = l8 * 8;
    float o[8];
#pragma unroll
    for (int q = 0; q < 8; q++) {
        int c = c0 + q;
        o[q] = fmaxf(fmaf(ax, Ws[c], fmaf(ay, Ws[HID + c], fmaf(az, Ws[2 * HID + c], Bs[c]))), 0.f);
    }
    *(float4*)&g_buf0[node * HID + c0]     = make_float4(o[0], o[1], o[2], o[3]);
    *(float4*)&g_buf0[node * HID + c0 + 4] = make_float4(o[4], o[5], o[6], o[7]);
}

// ---------------------------------------------------------------- GEMM 64x64
// g_gath[r] = bf16( (g_buf0 @ W)[r] * dinv[r] )
__global__ void gemm64_k(const float* __restrict__ W) {
    __shared__ float hs[64 * 65];
    __shared__ float ws[64 * 64];
    int t  = threadIdx.x;
    int rb = blockIdx.x * 64;
    {
        const float4* Wv = (const float4*)W;
        float4* wv = (float4*)ws;
#pragma unroll
        for (int q = 0; q < 4; q++) { int i = t + q * 256; wv[i] = Wv[i]; }
    }
#pragma unroll
    for (int q = 0; q < 4; q++) {
        int i = t + q * 256;
        int r = i >> 4, kq = (i & 15) << 2;
        float4 v = make_float4(0.f, 0.f, 0.f, 0.f);
        if (rb + r < N_NODES) v = *(const float4*)&g_buf0[(rb + r) * HID + kq];
        hs[r * 65 + kq]     = v.x;
        hs[r * 65 + kq + 1] = v.y;
        hs[r * 65 + kq + 2] = v.z;
        hs[r * 65 + kq + 3] = v.w;
    }
    __syncthreads();
    int tx = t & 15, ty = t >> 4;
    int c0 = tx * 4, r0 = ty * 4;
    float acc[4][4] = {};
#pragma unroll
    for (int k = 0; k < 64; k++) {
        float4 b = *(const float4*)&ws[k * 64 + c0];
        float a0 = hs[(r0 + 0) * 65 + k];
        float a1 = hs[(r0 + 1) * 65 + k];
        float a2 = hs[(r0 + 2) * 65 + k];
        float a3 = hs[(r0 + 3) * 65 + k];
        acc[0][0] += a0 * b.x; acc[0][1] += a0 * b.y; acc[0][2] += a0 * b.z; acc[0][3] += a0 * b.w;
        acc[1][0] += a1 * b.x; acc[1][1] += a1 * b.y; acc[1][2] += a1 * b.z; acc[1][3] += a1 * b.w;
        acc[2][0] += a2 * b.x; acc[2][1] += a2 * b.y; acc[2][2] += a2 * b.z; acc[2][3] += a2 * b.w;
        acc[3][0] += a3 * b.x; acc[3][1] += a3 * b.y; acc[3][2] += a3 * b.z; acc[3][3] += a3 * b.w;
    }
#pragma unroll
    for (int i = 0; i < 4; i++) {
        int r = rb + r0 + i;
        if (r < N_NODES) {
            float di = g_dinv[r];
            __nv_bfloat162 p0 = __floats2bfloat162_rn(acc[i][0] * di, acc[i][1] * di);
            __nv_bfloat162 p1 = __floats2bfloat162_rn(acc[i][2] * di, acc[i][3] * di);
            uint2 pk;
            pk.x = *(unsigned int*)&p0;
            pk.y = *(unsigned int*)&p1;
            *(uint2*)&g_gath[r * HID + c0] = pk;
        }
    }
}

// ---------------------------------------------------------------- Aggregation
// One warp per dst node; 4 groups x 8 lanes, bf16 rows, fp32 accumulate.
__global__ void agg_k(const float* __restrict__ bias) {
    int w    = (blockIdx.x * blockDim.x + threadIdx.x) >> 5;
    int lane = threadIdx.x & 31;
    if (w >= N_NODES) return;
    int grp = lane >> 3;          // 0..3
    int l8  = lane & 7;           // 0..7
    int ch0 = l8 * 8;             // first of 8 channels for this lane
    int s = g_rowptr[w];
    int e = g_rowptr[w + 1];

    float2 a0 = make_float2(0.f, 0.f), a1 = a0, a2 = a0, a3 = a0;

#define ACC_ROW(SRC)                                                          \
    {                                                                         \
        uint4 pk = *(const uint4*)&g_gath[(SRC) * HID + ch0];                 \
        float2 f0 = __bfloat1622float2(*(__nv_bfloat162*)&pk.x);              \
        float2 f1 = __bfloat1622float2(*(__nv_bfloat162*)&pk.y);              \
        float2 f2 = __bfloat1622float2(*(__nv_bfloat162*)&pk.z);              \
        float2 f3 = __bfloat1622float2(*(__nv_bfloat162*)&pk.w);              \
        a0.x += f0.x; a0.y += f0.y; a1.x += f1.x; a1.y += f1.y;               \
        a2.x += f2.x; a2.y += f2.y; a3.x += f3.x; a3.y += f3.y;               \
    }

    for (int base = s; base < e; base += 32) {
        int idx = base + lane;
        int cv = (idx < e) ? g_col[idx] : 0;
        int m = e - base;
        if (m > 32) m = 32;
        int j = 0;
        for (; j + 8 <= m; j += 8) {
            int s0 = __shfl_sync(0xffffffffu, cv, j + grp);
            int s1 = __shfl_sync(0xffffffffu, cv, j + 4 + grp);
            ACC_ROW(s0);
            ACC_ROW(s1);
        }
        for (; j < m; j += 4) {
            int jj = j + grp;
            int sj = __shfl_sync(0xffffffffu, cv, (jj < m) ? jj : (m - 1));
            if (jj < m) ACC_ROW(sj);
        }
    }
#undef ACC_ROW

#pragma unroll
    for (int off = 8; off <= 16; off <<= 1) {
        a0.x += __shfl_xor_sync(0xffffffffu, a0.x, off);
        a0.y += __shfl_xor_sync(0xffffffffu, a0.y, off);
        a1.x += __shfl_xor_sync(0xffffffffu, a1.x, off);
        a1.y += __shfl_xor_sync(0xffffffffu, a1.y, off);
        a2.x += __shfl_xor_sync(0xffffffffu, a2.x, off);
        a2.y += __shfl_xor_sync(0xffffffffu, a2.y, off);
        a3.x += __shfl_xor_sync(0xffffffffu, a3.x, off);
        a3.y += __shfl_xor_sync(0xffffffffu, a3.y, off);
    }

    if (grp == 0) {
        uint4 pk = *(const uint4*)&g_gath[w * HID + ch0];   // self loop
        float2 f0 = __bfloat1622float2(*(__nv_bfloat162*)&pk.x);
        float2 f1 = __bfloat1622float2(*(__nv_bfloat162*)&pk.y);
        float2 f2 = __bfloat1622float2(*(__nv_bfloat162*)&pk.z);
        float2 f3 = __bfloat1622float2(*(__nv_bfloat162*)&pk.w);
        a0.x += f0.x; a0.y += f0.y; a1.x += f1.x; a1.y += f1.y;
        a2.x += f2.x; a2.y += f2.y; a3.x += f3.x; a3.y += f3.y;

        float di = g_dinv[w];
        float4 bA = *(const float4*)&bias[ch0];
        float4 bB = *(const float4*)&bias[ch0 + 4];
        float4 r0, r1;
        r0.x = fmaxf(fmaf(a0.x, di, bA.x), 0.f);
        r0.y = fmaxf(fmaf(a0.y, di, bA.y), 0.f);
        r0.z = fmaxf(fmaf(a1.x, di, bA.z), 0.f);
        r0.w = fmaxf(fmaf(a1.y, di, bA.w), 0.f);
        r1.x = fmaxf(fmaf(a2.x, di, bB.x), 0.f);
        r1.y = fmaxf(fmaf(a2.y, di, bB.y), 0.f);
        r1.z = fmaxf(fmaf(a3.x, di, bB.z), 0.f);
        r1.w = fmaxf(fmaf(a3.y, di, bB.w), 0.f);
        *(float4*)&g_buf0[w * HID + ch0]     = r0;
        *(float4*)&g_buf0[w * HID + ch0 + 4] = r1;
    }
}

// ---------------------------------------------------------------- Pool + head (fused)
__global__ void poolfc_k(const int* __restrict__ batch,
                         const float* __restrict__ fc1w, const float* __restrict__ fc1b,
                         const float* __restrict__ fc2w, const float* __restrict__ fc2b,
                         float* __restrict__ out) {
    int g = blockIdx.x, t = threadIdx.x;   // 128 blocks x 256 thr
    __shared__ int lo_s, hi_s;
    if (t == 0) {
        int lo = 0, hi = N_NODES;
        while (lo < hi) { int m = (lo + hi) >> 1; if (batch[m] < g) lo = m + 1; else hi = m; }
        lo_s = lo;
        int lo2 = lo, hi2 = N_NODES;
        while (lo2 < hi2) { int m = (lo2 + hi2) >> 1; if (batch[m] < g + 1) lo2 = m + 1; else hi2 = m; }
        hi_s = lo2;
    }
    __syncthreads();
    int lo = lo_s, hi = hi_s;
    int c = t & 63, rg = t >> 6;
    float acc = 0.f;
    for (int r = lo + rg; r < hi; r += 4) acc += g_buf0[r * HID + c];
    __shared__ float sh[256];
    __shared__ float p[64];
    sh[t] = acc;
    __syncthreads();
    if (t < 64) {
        float s = sh[t] + sh[t + 64] + sh[t + 128] + sh[t + 192];
        float cntf = (float)(hi - lo);
        if (cntf < 1.f) cntf = 1.f;
        p[t] = s / cntf;
    }
    __syncthreads();
    // fc head on threads 0..127
    float v = 0.f;
    if (t < DENSE) {
        float a = fc1b[t];
#pragma unroll
        for (int k = 0; k < 64; k++) a = fmaf(p[k], fc1w[k * DENSE + t], a);
        v = fmaxf(a, 0.f) * fc2w[t];
    }
    __syncthreads();
    sh[t] = v;
    __syncthreads();
    if (t < 64) sh[t] += sh[t + 64];
    __syncthreads();
    if (t < 32) {
        float s = sh[t] + sh[t + 32];
#pragma unroll
        for (int off = 16; off; off >>= 1) s += __shfl_down_sync(0xffffffffu, s, off);
        if (t == 0) out[g] = s + fc2b[0];
    }
}

// ---------------------------------------------------------------- launch
extern "C" void kernel_launch(void* const* d_in, const int* in_sizes, int n_in,
                              void* d_out, int out_size) {
    const float* x     = (const float*)d_in[0];
    const int*   ei    = (const int*)d_in[1];
    const int*   batch = (const int*)d_in[2];
    const float* W0    = (const float*)d_in[3];
    const float* b0    = (const float*)d_in[4];
    const float* W1    = (const float*)d_in[5];
    const float* b1    = (const float*)d_in[6];
    const float* W2    = (const float*)d_in[7];
    const float* b2    = (const float*)d_in[8];
    const float* fc1w  = (const float*)d_in[9];
    const float* fc1b  = (const float*)d_in[10];
    const float* fc2w  = (const float*)d_in[11];
    const float* fc2b  = (const float*)d_in[12];
    float* out = (float*)d_out;

    // CSR build
    void* cnt_ptr = nullptr;
    cudaGetSymbolAddress(&cnt_ptr, g_cnt);
    cudaMemsetAsync(cnt_ptr, 0, N_NODES * sizeof(int));
    hist_k<<<(N_EDGES / 4 + 255) / 256, 256>>>(ei);
    scan1_k<<<NB, 1024>>>();
    scan3_k<<<(N_NODES + 255) / 256, 256>>>(x);
    fill_k<<<(N_EDGES / 4 + 255) / 256, 256>>>(ei);

    const int AGG_BLOCKS  = (N_NODES * 32 + 255) / 256;
    const int GEMM_BLOCKS = (N_NODES + 63) / 64;

    // Layer 0 (fused 3-ch aggregate + dense)
    agg_x_gemm0_k<<<(N_NODES * 8 + 255) / 256, 256>>>(W0, b0);
    // Layer 1
    gemm64_k<<<GEMM_BLOCKS, 256>>>(W1);
    agg_k<<<AGG_BLOCKS, 256>>>(b1);
    // Layer 2
    gemm64_k<<<GEMM_BLOCKS, 256>>>(W2);
    agg_k<<<AGG_BLOCKS, 256>>>(b2);

    // Pool + head
    poolfc_k<<<NGRAPH, 256>>>(batch, fc1w, fc1b, fc2w, fc2b, out);
}